// round 10
// baseline (speedup 1.0000x reference)
#include <cuda_runtime.h>
#include <cuda_bf16.h>
#include <cstdint>

#define NSTATE (1u << 23)

__device__ float g_scratch[1u << 24];
__device__ __nv_bfloat16 g_ubf[262144];   // 4 gates x 4 matrices x 16384 bf16

#define SMEM_BYTES_HI 196608u   // gate 3 kernel (unchanged R9)
#define SMEM_BYTES_LO 98304u    // gates 0-2: U-half 64KB + 2 x 16KB state buffers
#define SGN 0x80008000u

// gate 3 layout: U-half tiles [0,65536), state B buffers 65536 + buf*65536
#define BH_OFF 65536u
// gates 0-2 (2-CTA version): U-half [0,65536) 4 x 16KB, state 65536 + buf*16384 (4 x 4KB)
#define SL_OFF 65536u

__device__ __forceinline__ uint32_t smem_u32(const void* p) {
    uint32_t a;
    asm("{ .reg .u64 t; cvta.to.shared.u64 t, %1; cvt.u32.u64 %0, t; }" : "=r"(a) : "l"(p));
    return a;
}

#define CPASYNC16(saddr, gptr)                                                  \
    asm volatile("cp.async.cg.shared.global [%0], [%1], 16;"                    \
        :: "r"(saddr), "l"(gptr) : "memory")

#define LDM4(r, addr)                                                           \
    asm volatile("ldmatrix.sync.aligned.m8n8.x4.shared.b16 {%0,%1,%2,%3}, [%4];"\
        : "=r"((r)[0]), "=r"((r)[1]), "=r"((r)[2]), "=r"((r)[3]) : "r"(addr))

#define LDM2(r, addr)                                                           \
    asm volatile("ldmatrix.sync.aligned.m8n8.x2.shared.b16 {%0,%1}, [%2];"      \
        : "=r"((r)[0]), "=r"((r)[1]) : "r"(addr))

#define LDM4T(r, addr)                                                          \
    asm volatile("ldmatrix.sync.aligned.m8n8.x4.trans.shared.b16 {%0,%1,%2,%3}, [%4];"\
        : "=r"((r)[0]), "=r"((r)[1]), "=r"((r)[2]), "=r"((r)[3]) : "r"(addr))

#define MMA(C, A, b0v, b1v)                                                     \
    asm volatile("mma.sync.aligned.m16n8k16.row.col.f32.bf16.bf16.f32 "         \
        "{%0,%1,%2,%3}, {%4,%5,%6,%7}, {%8,%9}, {%0,%1,%2,%3};"                 \
        : "+f"((C)[0]), "+f"((C)[1]), "+f"((C)[2]), "+f"((C)[3])                \
        : "r"((A)[0]), "r"((A)[1]), "r"((A)[2]), "r"((A)[3]), "r"(b0v), "r"(b1v))

// 12-MMA (wide-B form): ch1 = A_r*B_r - A_i*B_i ; ch0 = A_i*B_r + A_r*B_i
#define MMA12(A0, J2)                                                           \
    MMA(acc1[A0], af[0], bf[0][J2], bf[0][(J2) + 2]);                           \
    MMA(acc1[A0], af[0], bf[1][J2], bf[1][(J2) + 2]);                           \
    MMA(acc1[A0], af[1], bf[0][J2], bf[0][(J2) + 2]);                           \
    MMA(acc1[A0], naf2,  bf[2][J2], bf[2][(J2) + 2]);                           \
    MMA(acc1[A0], naf2,  bf[3][J2], bf[3][(J2) + 2]);                           \
    MMA(acc1[A0], naf3,  bf[2][J2], bf[2][(J2) + 2]);                           \
    MMA(acc0[A0], af[2], bf[0][J2], bf[0][(J2) + 2]);                           \
    MMA(acc0[A0], af[2], bf[1][J2], bf[1][(J2) + 2]);                           \
    MMA(acc0[A0], af[3], bf[0][J2], bf[0][(J2) + 2]);                           \
    MMA(acc0[A0], af[0], bf[2][J2], bf[2][(J2) + 2]);                           \
    MMA(acc0[A0], af[0], bf[3][J2], bf[3][(J2) + 2]);                           \
    MMA(acc0[A0], af[1], bf[2][J2], bf[2][(J2) + 2]);

// fp32 x8 -> bf16 hi (16B) + bf16 lo (16B)
__device__ __forceinline__ void cvt8(float4 x, float4 y, uint4* hi, uint4* lo) {
    float f[8] = {x.x, x.y, x.z, x.w, y.x, y.y, y.z, y.w};
    uint32_t h[8], l[8];
    #pragma unroll
    for (int i = 0; i < 8; ++i) {
        __nv_bfloat16 hb = __float2bfloat16(f[i]);
        h[i] = (uint32_t)__bfloat16_as_ushort(hb);
        l[i] = (uint32_t)__bfloat16_as_ushort(__float2bfloat16(f[i] - __bfloat162float(hb)));
    }
    *hi = make_uint4(h[0] | (h[1] << 16), h[2] | (h[3] << 16),
                     h[4] | (h[5] << 16), h[6] | (h[7] << 16));
    *lo = make_uint4(l[0] | (l[1] << 16), l[2] | (l[3] << 16),
                     l[4] | (l[5] << 16), l[6] | (l[7] << 16));
}

// ---------------------------------------------------------------------------
__global__ void prep_u(const float* __restrict__ U)
{
    const int i = blockIdx.x * 256 + threadIdx.x;   // 131072
    const int a = i & 127, k = (i >> 7) & 127, c = (i >> 14) & 1, g = i >> 15;
    const float x = U[i];
    const __nv_bfloat16 hi = __float2bfloat16(x);
    const __nv_bfloat16 lo = __float2bfloat16(x - __bfloat162float(hi));
    const int h = k * 128 + (((a >> 3) ^ (k & 7)) << 3) + (a & 7);
    g_ubf[g * 65536 + (c * 2 + 0) * 16384 + h] = hi;
    g_ubf[g * 65536 + (c * 2 + 1) * 16384 + h] = lo;
}

// ---------------------------------------------------------------------------
// Gates 0-2, 2 CTAs/SM: each CTA owns one k-half of U (64 out-cols, 64KB)
// and streams 16-row state items through 2 x 16KB buffers. 296 CTAs, 256 thr.
// 8 warps, each a 16(m) x 8(k) output tile.
__global__ void __launch_bounds__(256, 2)
gate_low2(const float* __restrict__ in, float* __restrict__ out,
          const __nv_bfloat16* __restrict__ img)
{
    extern __shared__ char smem[];
    const uint32_t sb = smem_u32(smem);
    const int t = threadIdx.x, lane = t & 31, w = t >> 5;
    const int khalf = blockIdx.x & 1;
    const int worker = blockIdx.x >> 1;   // 0..147

    // stage this CTA's U half: rows [khalf*64, +64) of each of 4 mats (64KB)
    {
        const uint4* src = (const uint4*)img;
        #pragma unroll
        for (int j = 0; j < 16; ++j) {
            const int idx = t + 256 * j;             // 0..4095 (16B units)
            const int m = idx >> 10, within = idx & 1023;
            CPASYNC16(sb + (uint32_t)idx * 16u, src + m * 2048 + khalf * 1024 + within);
        }
        asm volatile("cp.async.commit_group;" ::: "memory");
    }

    int item = worker;                    // 4096 items of 16 rows
    // first item convert (512 slots, 2 per thread)
    {
        const size_t base = (size_t)item * 2048;
        #pragma unroll
        for (int s = 0; s < 2; ++s) {
            const int slot = t + 256 * s;
            const int c = slot & 15, r = (slot >> 4) & 15, ch = slot >> 8;
            const float4* p = (const float4*)(in + (size_t)ch * NSTATE + base + r * 128 + c * 8);
            uint4 hi, lo;
            cvt8(p[0], p[1], &hi, &lo);
            char* wp = smem + SL_OFF + (ch * 2) * 4096 + r * 256 + ((c ^ (r & 7)) * 16);
            *(uint4*)wp = hi;
            *(uint4*)(wp + 4096) = lo;
        }
    }
    asm volatile("cp.async.wait_group 0;" ::: "memory");
    __syncthreads();

    const int ar = lane & 15, acl = lane >> 4, ar7 = ar & 7;
    const int bl = lane & 15;
    const int brow = w * 8 + (bl & 7);    // U row = output k within half
    const int bk = (bl >> 3) & 1;         // k-chunk selector for ldmatrix x2
    const uint32_t bbase = sb + (uint32_t)brow * 256u;
    const int br7 = brow & 7;
    const int rg = lane >> 2, tg = lane & 3;

    uint32_t buf = 0;
    for (; item < 4096; item += 148) {
        const int next = item + 148;
        const bool hasnext = next < 4096;
        float4 stg[4];
        if (hasnext) {
            const size_t base = (size_t)next * 2048;
            #pragma unroll
            for (int s = 0; s < 2; ++s) {
                const int slot = t + 256 * s;
                const int c = slot & 15, r = (slot >> 4) & 15, ch = slot >> 8;
                const float4* p = (const float4*)(in + (size_t)ch * NSTATE + base + r * 128 + c * 8);
                stg[2 * s] = p[0];
                stg[2 * s + 1] = p[1];
            }
        }

        float acc0[4], acc1[4];
        #pragma unroll
        for (int q = 0; q < 4; ++q) { acc0[q] = 0.f; acc1[q] = 0.f; }

        const uint32_t abase = sb + SL_OFF + buf * 16384u + (uint32_t)ar * 256u;
        #pragma unroll 1
        for (int ks = 0; ks < 8; ++ks) {
            uint32_t af[4][4], naf2[4], naf3[4];
            const uint32_t aa = abase + (uint32_t)(((ks * 2 + acl) ^ ar7) << 4);
            LDM4(af[0], aa);              // Sr_hi
            LDM4(af[1], aa + 4096);       // Sr_lo
            LDM4(af[2], aa + 8192);       // Si_hi
            LDM4(af[3], aa + 12288);      // Si_lo
            #pragma unroll
            for (int q = 0; q < 4; ++q) { naf2[q] = af[2][q] ^ SGN; naf3[q] = af[3][q] ^ SGN; }

            uint32_t bu[4][2];            // Ur_hi, Ur_lo, Ui_hi, Ui_lo (n=8 frags)
            const uint32_t ba = bbase + (uint32_t)(((ks * 2 + bk) ^ br7) << 4);
            LDM2(bu[0], ba);
            LDM2(bu[1], ba + 16384);
            LDM2(bu[2], ba + 32768);
            LDM2(bu[3], ba + 49152);

            // ch1 = Sr*Ur - Si*Ui ; ch0 = Si*Ur + Sr*Ui (hi*hi + hi*lo + lo*hi)
            MMA(acc1, af[0], bu[0][0], bu[0][1]);
            MMA(acc1, af[0], bu[1][0], bu[1][1]);
            MMA(acc1, af[1], bu[0][0], bu[0][1]);
            MMA(acc1, naf2,  bu[2][0], bu[2][1]);
            MMA(acc1, naf2,  bu[3][0], bu[3][1]);
            MMA(acc1, naf3,  bu[2][0], bu[2][1]);
            MMA(acc0, af[2], bu[0][0], bu[0][1]);
            MMA(acc0, af[2], bu[1][0], bu[1][1]);
            MMA(acc0, af[3], bu[0][0], bu[0][1]);
            MMA(acc0, af[0], bu[2][0], bu[2][1]);
            MMA(acc0, af[0], bu[3][0], bu[3][1]);
            MMA(acc0, af[1], bu[2][0], bu[2][1]);
        }

        if (hasnext) {
            #pragma unroll
            for (int s = 0; s < 2; ++s) {
                const int slot = t + 256 * s;
                const int c = slot & 15, r = (slot >> 4) & 15, ch = slot >> 8;
                uint4 hi, lo;
                cvt8(stg[2 * s], stg[2 * s + 1], &hi, &lo);
                char* wp = smem + SL_OFF + (buf ^ 1u) * 16384u + (ch * 2) * 4096 + r * 256
                         + ((c ^ (r & 7)) * 16);
                *(uint4*)wp = hi;
                *(uint4*)(wp + 4096) = lo;
            }
        }

        {
            const size_t row0 = (size_t)item * 16 + rg;
            const int n = khalf * 64 + w * 8 + tg * 2;
            float* o0 = out;
            float* o1 = out + NSTATE;
            *(float2*)(o0 + row0 * 128 + n)       = make_float2(acc0[0], acc0[1]);
            *(float2*)(o0 + (row0 + 8) * 128 + n) = make_float2(acc0[2], acc0[3]);
            *(float2*)(o1 + row0 * 128 + n)       = make_float2(acc1[0], acc1[1]);
            *(float2*)(o1 + (row0 + 8) * 128 + n) = make_float2(acc1[2], acc1[3]);
        }
        __syncthreads();
        buf ^= 1u;
    }
}

// ---------------------------------------------------------------------------
// Gate 3 (unchanged R9): persistent 512 threads; A = U k-half resident.
__global__ void __launch_bounds__(512, 1)
gate_highp(const float* __restrict__ in, float* __restrict__ out,
           const __nv_bfloat16* __restrict__ img)
{
    extern __shared__ char smem[];
    const uint32_t sb = smem_u32(smem);
    const int t = threadIdx.x, lane = t & 31, w = t >> 5;
    const int khalf = blockIdx.x & 1;
    const int pairid = blockIdx.x >> 1;   // 0..73

    {
        const uint4* src = (const uint4*)img;
        #pragma unroll
        for (int j = 0; j < 8; ++j) {
            const int idx = t + 512 * j;              // 0..4095
            const int m = idx >> 10, within = idx & 1023;
            CPASYNC16(sb + (uint32_t)idx * 16u, src + m * 2048 + khalf * 1024 + within);
        }
        asm volatile("cp.async.commit_group;" ::: "memory");
    }

    int widx = pairid;                    // 1024 = 512 chunks x 2 l-halves
    {
        const int chunk = widx >> 1, lh = widx & 1;
        const size_t cb = (size_t)chunk * 16384;
        #pragma unroll
        for (int s = 0; s < 4; ++s) {
            const int slot = t + 512 * s;
            const int c = slot & 7, a = (slot >> 3) & 127, ch = slot >> 10;
            const float4* p = (const float4*)(in + (size_t)ch * NSTATE + cb + a * 128 + lh * 64 + c * 8);
            uint4 hi, lo;
            cvt8(p[0], p[1], &hi, &lo);
            char* wp = smem + BH_OFF + (ch * 2) * 16384 + a * 128 + ((c ^ (a & 7)) * 16);
            *(uint4*)wp = hi;
            *(uint4*)(wp + 16384) = lo;
        }
    }
    asm volatile("cp.async.wait_group 0;" ::: "memory");
    __syncthreads();

    const int mrow0 = (w & 3) * 16, ncol0 = (w >> 2) * 16;
    const int ar = mrow0 + (lane & 15), acl = lane >> 4, ar7 = ar & 7;
    const int br_off = (lane & 7) + ((lane & 16) >> 1), bcl = (lane >> 3) & 1;
    const int rg = lane >> 2, tg = lane & 3;
    const uint32_t abase = sb + (uint32_t)ar * 256u;
    const int cidx = (ncol0 >> 3) + bcl;

    uint32_t buf = 0;
    for (; widx < 1024; widx += 74) {
        const int chunk = widx >> 1, lh = widx & 1;
        const size_t cb = (size_t)chunk * 16384;
        const int nwidx = widx + 74;
        const bool hasnext = nwidx < 1024;
        const int nchunk = nwidx >> 1, nlh = nwidx & 1;
        const size_t ncb = (size_t)nchunk * 16384;

        float4 stg[4];
        if (hasnext) {
            #pragma unroll
            for (int s = 0; s < 2; ++s) {
                const int slot = t + 512 * s;
                const int c = slot & 7, a = (slot >> 3) & 127, ch = slot >> 10;
                const float4* p = (const float4*)(in + (size_t)ch * NSTATE + ncb + a * 128 + nlh * 64 + c * 8);
                stg[2 * s] = p[0];
                stg[2 * s + 1] = p[1];
            }
        }

        float acc0[2][4], acc1[2][4];
        #pragma unroll
        for (int j = 0; j < 2; ++j)
            #pragma unroll
            for (int q = 0; q < 4; ++q) { acc0[j][q] = 0.f; acc1[j][q] = 0.f; }

        const uint32_t bbuf = sb + BH_OFF + buf * 65536u;
        #pragma unroll 1
        for (int ks = 0; ks < 8; ++ks) {
            uint32_t af[4][4], naf2[4], naf3[4];
            const uint32_t aa = abase + (uint32_t)(((ks * 2 + acl) ^ ar7) << 4);
            LDM4(af[0], aa);
            LDM4(af[1], aa + 16384);
            LDM4(af[2], aa + 32768);
            LDM4(af[3], aa + 49152);
            #pragma unroll
            for (int q = 0; q < 4; ++q) { naf2[q] = af[2][q] ^ SGN; naf3[q] = af[3][q] ^ SGN; }

            uint32_t bf[4][4];
            const int row = ks * 16 + br_off;
            const uint32_t ba = bbuf + (uint32_t)row * 128u
                              + (uint32_t)((cidx ^ (row & 7)) << 4);
            LDM4T(bf[0], ba);
            LDM4T(bf[1], ba + 16384);
            LDM4T(bf[2], ba + 32768);
            LDM4T(bf[3], ba + 49152);
            MMA12(0, 0)
            MMA12(1, 1)
        }

        if (hasnext) {
            #pragma unroll
            for (int s = 0; s < 2; ++s) {
                const int slot = t + 512 * s;
                const int c = slot & 7, a = (slot >> 3) & 127, ch = slot >> 10;
                uint4 hi, lo;
                cvt8(stg[2 * s], stg[2 * s + 1], &hi, &lo);
                char* wp = smem + BH_OFF + (buf ^ 1u) * 65536u + (ch * 2) * 16384 + a * 128
                         + ((c ^ (a & 7)) * 16);
                *(uint4*)wp = hi;
                *(uint4*)(wp + 16384) = lo;
            }
            #pragma unroll
            for (int s = 2; s < 4; ++s) {
                const int slot = t + 512 * s;
                const int c = slot & 7, a = (slot >> 3) & 127, ch = slot >> 10;
                const float4* p = (const float4*)(in + (size_t)ch * NSTATE + ncb + a * 128 + nlh * 64 + c * 8);
                uint4 hi, lo;
                cvt8(p[0], p[1], &hi, &lo);
                char* wp = smem + BH_OFF + (buf ^ 1u) * 65536u + (ch * 2) * 16384 + a * 128
                         + ((c ^ (a & 7)) * 16);
                *(uint4*)wp = hi;
                *(uint4*)(wp + 16384) = lo;
            }
        }

        {
            const size_t row0 = (size_t)khalf * 64 + mrow0 + rg;
            float* o0 = out + cb;
            float* o1 = out + NSTATE + cb;
            #pragma unroll
            for (int j = 0; j < 2; ++j) {
                const int n = lh * 64 + ncol0 + j * 8 + tg * 2;
                *(float2*)(o0 + row0 * 128 + n)       = make_float2(acc0[j][0], acc0[j][1]);
                *(float2*)(o0 + (row0 + 8) * 128 + n) = make_float2(acc0[j][2], acc0[j][3]);
                *(float2*)(o1 + row0 * 128 + n)       = make_float2(acc1[j][0], acc1[j][1]);
                *(float2*)(o1 + (row0 + 8) * 128 + n) = make_float2(acc1[j][2], acc1[j][3]);
            }
        }
        __syncthreads();
        buf ^= 1u;
    }
}

// ---------------------------------------------------------------------------
extern "C" void kernel_launch(void* const* d_in, const int* in_sizes, int n_in,
                              void* d_out, int out_size)
{
    const float* state = (const float*)d_in[0];
    const float* U     = (const float*)d_in[1];
    if (n_in >= 2 && in_sizes[0] < in_sizes[1]) {
        const float* tmp = state; state = U; U = tmp;
    }
    float* out = (float*)d_out;

    float* scratch = nullptr;
    cudaGetSymbolAddress((void**)&scratch, g_scratch);
    __nv_bfloat16* ubf = nullptr;
    cudaGetSymbolAddress((void**)&ubf, g_ubf);

    cudaFuncSetAttribute(gate_low2,  cudaFuncAttributeMaxDynamicSharedMemorySize, (int)SMEM_BYTES_LO);
    cudaFuncSetAttribute(gate_highp, cudaFuncAttributeMaxDynamicSharedMemorySize, (int)SMEM_BYTES_HI);

    prep_u<<<512, 256>>>(U);
    gate_low2<<<296, 256, SMEM_BYTES_LO>>>(state,   scratch, ubf);            // gate 0
    gate_low2<<<296, 256, SMEM_BYTES_LO>>>(scratch, out,     ubf + 65536);    // gate 1
    gate_low2<<<296, 256, SMEM_BYTES_LO>>>(out,     scratch, ubf + 131072);   // gate 2
    gate_highp<<<148, 512, SMEM_BYTES_HI>>>(scratch, out,    ubf + 196608);   // gate 3
}

// round 11
// speedup vs baseline: 1.0310x; 1.0310x over previous
#include <cuda_runtime.h>
#include <cuda_bf16.h>
#include <cstdint>

#define NSTATE (1u << 23)

__device__ float g_scratch[1u << 24];
__device__ __nv_bfloat16 g_ubf[262144];   // 4 gates x 4 matrices x 16384 bf16

#define SMEM_BYTES 196608u
#define SGN 0x80008000u

// gates 0-2: U tiles [0,131072) (4 x 32768), state A buffers 131072 + buf*32768 (4 x 8192)
#define AL_OFF 131072u
// gate 3: U-half tiles [0,65536) (4 x 16384), state B buffers 65536 + buf*65536 (4 x 16384)
#define BH_OFF 65536u

__device__ __forceinline__ uint32_t smem_u32(const void* p) {
    uint32_t a;
    asm("{ .reg .u64 t; cvta.to.shared.u64 t, %1; cvt.u32.u64 %0, t; }" : "=r"(a) : "l"(p));
    return a;
}

#define CPASYNC16(saddr, gptr)                                                  \
    asm volatile("cp.async.cg.shared.global [%0], [%1], 16;"                    \
        :: "r"(saddr), "l"(gptr) : "memory")

#define LDM4(r, addr)                                                           \
    asm volatile("ldmatrix.sync.aligned.m8n8.x4.shared.b16 {%0,%1,%2,%3}, [%4];"\
        : "=r"((r)[0]), "=r"((r)[1]), "=r"((r)[2]), "=r"((r)[3]) : "r"(addr))

#define LDM4T(r, addr)                                                          \
    asm volatile("ldmatrix.sync.aligned.m8n8.x4.trans.shared.b16 {%0,%1,%2,%3}, [%4];"\
        : "=r"((r)[0]), "=r"((r)[1]), "=r"((r)[2]), "=r"((r)[3]) : "r"(addr))

#define MMA(C, A, b0v, b1v)                                                     \
    asm volatile("mma.sync.aligned.m16n8k16.row.col.f32.bf16.bf16.f32 "         \
        "{%0,%1,%2,%3}, {%4,%5,%6,%7}, {%8,%9}, {%0,%1,%2,%3};"                 \
        : "+f"((C)[0]), "+f"((C)[1]), "+f"((C)[2]), "+f"((C)[3])                \
        : "r"((A)[0]), "r"((A)[1]), "r"((A)[2]), "r"((A)[3]), "r"(b0v), "r"(b1v))

// 12-MMA block on explicit fragment sets:
// ch1 = A_r*B_r - A_i*B_i ; ch0 = A_i*B_r + A_r*B_i (hi*hi + hi*lo + lo*hi each)
#define MMA12P(ACC0, ACC1, AF, N2, N3, BF, J2)                                  \
    MMA(ACC1, AF[0], BF[0][J2], BF[0][(J2) + 2]);                               \
    MMA(ACC1, AF[0], BF[1][J2], BF[1][(J2) + 2]);                               \
    MMA(ACC1, AF[1], BF[0][J2], BF[0][(J2) + 2]);                               \
    MMA(ACC1, N2,    BF[2][J2], BF[2][(J2) + 2]);                               \
    MMA(ACC1, N2,    BF[3][J2], BF[3][(J2) + 2]);                               \
    MMA(ACC1, N3,    BF[2][J2], BF[2][(J2) + 2]);                               \
    MMA(ACC0, AF[2], BF[0][J2], BF[0][(J2) + 2]);                               \
    MMA(ACC0, AF[2], BF[1][J2], BF[1][(J2) + 2]);                               \
    MMA(ACC0, AF[3], BF[0][J2], BF[0][(J2) + 2]);                               \
    MMA(ACC0, AF[0], BF[2][J2], BF[2][(J2) + 2]);                               \
    MMA(ACC0, AF[0], BF[3][J2], BF[3][(J2) + 2]);                               \
    MMA(ACC0, AF[1], BF[2][J2], BF[2][(J2) + 2]);

// fp32 x8 -> bf16 hi (16B) + bf16 lo (16B)
__device__ __forceinline__ void cvt8(float4 x, float4 y, uint4* hi, uint4* lo) {
    float f[8] = {x.x, x.y, x.z, x.w, y.x, y.y, y.z, y.w};
    uint32_t h[8], l[8];
    #pragma unroll
    for (int i = 0; i < 8; ++i) {
        __nv_bfloat16 hb = __float2bfloat16(f[i]);
        h[i] = (uint32_t)__bfloat16_as_ushort(hb);
        l[i] = (uint32_t)__bfloat16_as_ushort(__float2bfloat16(f[i] - __bfloat162float(hb)));
    }
    *hi = make_uint4(h[0] | (h[1] << 16), h[2] | (h[3] << 16),
                     h[4] | (h[5] << 16), h[6] | (h[7] << 16));
    *lo = make_uint4(l[0] | (l[1] << 16), l[2] | (l[3] << 16),
                     l[4] | (l[5] << 16), l[6] | (l[7] << 16));
}

// ---------------------------------------------------------------------------
__global__ void prep_u(const float* __restrict__ U)
{
    const int i = blockIdx.x * 256 + threadIdx.x;   // 131072
    const int a = i & 127, k = (i >> 7) & 127, c = (i >> 14) & 1, g = i >> 15;
    const float x = U[i];
    const __nv_bfloat16 hi = __float2bfloat16(x);
    const __nv_bfloat16 lo = __float2bfloat16(x - __bfloat162float(hi));
    const int h = k * 128 + (((a >> 3) ^ (k & 7)) << 3) + (a & 7);
    g_ubf[g * 65536 + (c * 2 + 0) * 16384 + h] = hi;
    g_ubf[g * 65536 + (c * 2 + 1) * 16384 + h] = lo;
}

// ---------------------------------------------------------------------------
// Gates 0-2, persistent, 512 threads: U resident; 32-row chunks double-buffered.
// 16 warps, 16x16 tiles; fragment registers double-buffered across ks.
__global__ void __launch_bounds__(512, 1)
gate_lowp(const float* __restrict__ in, float* __restrict__ out,
          const __nv_bfloat16* __restrict__ img)
{
    extern __shared__ char smem[];
    const uint32_t sb = smem_u32(smem);
    const int t = threadIdx.x, lane = t & 31, w = t >> 5;

    // stage U image once (128KB, pre-swizzled)
    {
        const uint4* src = (const uint4*)img;
        #pragma unroll
        for (int j = 0; j < 16; ++j) {
            const int idx = t + 512 * j;
            CPASYNC16(sb + (uint32_t)idx * 16u, src + idx);
        }
        asm volatile("cp.async.commit_group;" ::: "memory");
    }

    int item = blockIdx.x;
    // first chunk convert (1024 slots, 2 per thread)
    {
        const size_t base = (size_t)item * 4096;
        #pragma unroll
        for (int s = 0; s < 2; ++s) {
            const int slot = t + 512 * s;
            const int c = slot & 15, r = (slot >> 4) & 31, ch = slot >> 9;
            const float4* p = (const float4*)(in + (size_t)ch * NSTATE + base + r * 128 + c * 8);
            uint4 hi, lo;
            cvt8(p[0], p[1], &hi, &lo);
            char* wp = smem + AL_OFF + (ch * 2) * 8192 + r * 256 + ((c ^ (r & 7)) * 16);
            *(uint4*)wp = hi;
            *(uint4*)(wp + 8192) = lo;
        }
    }
    asm volatile("cp.async.wait_group 0;" ::: "memory");
    __syncthreads();

    const int mrow0 = (w & 1) * 16, ncol0 = (w >> 1) * 16;
    const int ar = mrow0 + (lane & 15), acl = lane >> 4, ar7 = ar & 7;
    const int br_off = lane & 15, bcl = lane >> 4;
    const int rg = lane >> 2, tg = lane & 3;
    const int brow = ncol0 + br_off;
    const uint32_t bbase = sb + (uint32_t)brow * 256u;
    const int br7 = brow & 7;

    uint32_t buf = 0;
    for (; item < 2048; item += 148) {
        const int next = item + 148;
        const bool hasnext = next < 2048;
        float4 stg[4];
        if (hasnext) {
            const size_t base = (size_t)next * 4096;
            #pragma unroll
            for (int s = 0; s < 2; ++s) {
                const int slot = t + 512 * s;
                const int c = slot & 15, r = (slot >> 4) & 31, ch = slot >> 9;
                const float4* p = (const float4*)(in + (size_t)ch * NSTATE + base + r * 128 + c * 8);
                stg[2 * s] = p[0];
                stg[2 * s + 1] = p[1];
            }
        }

        float acc0[2][4], acc1[2][4];
        #pragma unroll
        for (int j = 0; j < 2; ++j)
            #pragma unroll
            for (int q = 0; q < 4; ++q) { acc0[j][q] = 0.f; acc1[j][q] = 0.f; }

        const uint32_t abase = sb + AL_OFF + buf * 32768u + (uint32_t)ar * 256u;

        // fragment double buffers
        uint32_t af[2][4][4], bfr[2][4][4];
        {
            const uint32_t aa = abase + (uint32_t)((acl ^ ar7) << 4);
            LDM4(af[0][0], aa);
            LDM4(af[0][1], aa + 8192);
            LDM4(af[0][2], aa + 16384);
            LDM4(af[0][3], aa + 24576);
            const uint32_t ba = bbase + (uint32_t)((bcl ^ br7) << 4);
            LDM4(bfr[0][0], ba);
            LDM4(bfr[0][1], ba + 32768);
            LDM4(bfr[0][2], ba + 65536);
            LDM4(bfr[0][3], ba + 98304);
        }

        #pragma unroll
        for (int ks = 0; ks < 8; ++ks) {
            const int cur = ks & 1, nxt = cur ^ 1;
            if (ks < 7) {
                const uint32_t aa = abase + (uint32_t)((((ks + 1) * 2 + acl) ^ ar7) << 4);
                LDM4(af[nxt][0], aa);
                LDM4(af[nxt][1], aa + 8192);
                LDM4(af[nxt][2], aa + 16384);
                LDM4(af[nxt][3], aa + 24576);
                const uint32_t ba = bbase + (uint32_t)((((ks + 1) * 2 + bcl) ^ br7) << 4);
                LDM4(bfr[nxt][0], ba);
                LDM4(bfr[nxt][1], ba + 32768);
                LDM4(bfr[nxt][2], ba + 65536);
                LDM4(bfr[nxt][3], ba + 98304);
            }
            uint32_t naf2[4], naf3[4];
            #pragma unroll
            for (int q = 0; q < 4; ++q) {
                naf2[q] = af[cur][2][q] ^ SGN;
                naf3[q] = af[cur][3][q] ^ SGN;
            }
            MMA12P(acc0[0], acc1[0], af[cur], naf2, naf3, bfr[cur], 0)
            MMA12P(acc0[1], acc1[1], af[cur], naf2, naf3, bfr[cur], 1)
        }

        if (hasnext) {
            #pragma unroll
            for (int s = 0; s < 2; ++s) {
                const int slot = t + 512 * s;
                const int c = slot & 15, r = (slot >> 4) & 31, ch = slot >> 9;
                uint4 hi, lo;
                cvt8(stg[2 * s], stg[2 * s + 1], &hi, &lo);
                char* wp = smem + AL_OFF + (buf ^ 1u) * 32768u + (ch * 2) * 8192 + r * 256
                         + ((c ^ (r & 7)) * 16);
                *(uint4*)wp = hi;
                *(uint4*)(wp + 8192) = lo;
            }
        }

        {
            const size_t row0 = (size_t)item * 32 + mrow0 + rg;
            float* o0 = out;
            float* o1 = out + NSTATE;
            #pragma unroll
            for (int j = 0; j < 2; ++j) {
                const int n = ncol0 + j * 8 + tg * 2;
                *(float2*)(o0 + row0 * 128 + n)       = make_float2(acc0[j][0], acc0[j][1]);
                *(float2*)(o0 + (row0 + 8) * 128 + n) = make_float2(acc0[j][2], acc0[j][3]);
                *(float2*)(o1 + row0 * 128 + n)       = make_float2(acc1[j][0], acc1[j][1]);
                *(float2*)(o1 + (row0 + 8) * 128 + n) = make_float2(acc1[j][2], acc1[j][3]);
            }
        }
        __syncthreads();
        buf ^= 1u;
    }
}

// ---------------------------------------------------------------------------
// Gate 3, persistent, 512 threads: A = U k-half resident; B double-buffered.
// 16 warps, 16x16 tiles; fragment registers double-buffered across ks.
__global__ void __launch_bounds__(512, 1)
gate_highp(const float* __restrict__ in, float* __restrict__ out,
           const __nv_bfloat16* __restrict__ img)
{
    extern __shared__ char smem[];
    const uint32_t sb = smem_u32(smem);
    const int t = threadIdx.x, lane = t & 31, w = t >> 5;
    const int khalf = blockIdx.x & 1;
    const int pairid = blockIdx.x >> 1;   // 0..73

    {
        const uint4* src = (const uint4*)img;
        #pragma unroll
        for (int j = 0; j < 8; ++j) {
            const int idx = t + 512 * j;              // 0..4095
            const int m = idx >> 10, within = idx & 1023;
            CPASYNC16(sb + (uint32_t)idx * 16u, src + m * 2048 + khalf * 1024 + within);
        }
        asm volatile("cp.async.commit_group;" ::: "memory");
    }

    int widx = pairid;                    // 1024 = 512 chunks x 2 l-halves
    {
        const int chunk = widx >> 1, lh = widx & 1;
        const size_t cb = (size_t)chunk * 16384;
        #pragma unroll
        for (int s = 0; s < 4; ++s) {
            const int slot = t + 512 * s;
            const int c = slot & 7, a = (slot >> 3) & 127, ch = slot >> 10;
            const float4* p = (const float4*)(in + (size_t)ch * NSTATE + cb + a * 128 + lh * 64 + c * 8);
            uint4 hi, lo;
            cvt8(p[0], p[1], &hi, &lo);
            char* wp = smem + BH_OFF + (ch * 2) * 16384 + a * 128 + ((c ^ (a & 7)) * 16);
            *(uint4*)wp = hi;
            *(uint4*)(wp + 16384) = lo;
        }
    }
    asm volatile("cp.async.wait_group 0;" ::: "memory");
    __syncthreads();

    const int mrow0 = (w & 3) * 16, ncol0 = (w >> 2) * 16;
    const int ar = mrow0 + (lane & 15), acl = lane >> 4, ar7 = ar & 7;
    const int br_off = (lane & 7) + ((lane & 16) >> 1), bcl = (lane >> 3) & 1;
    const int rg = lane >> 2, tg = lane & 3;
    const uint32_t abase = sb + (uint32_t)ar * 256u;
    const int cidx = (ncol0 >> 3) + bcl;

    uint32_t buf = 0;
    for (; widx < 1024; widx += 74) {
        const int chunk = widx >> 1, lh = widx & 1;
        const size_t cb = (size_t)chunk * 16384;
        const int nwidx = widx + 74;
        const bool hasnext = nwidx < 1024;
        const int nchunk = nwidx >> 1, nlh = nwidx & 1;
        const size_t ncb = (size_t)nchunk * 16384;

        float4 stg[4];
        if (hasnext) {
            #pragma unroll
            for (int s = 0; s < 2; ++s) {
                const int slot = t + 512 * s;
                const int c = slot & 7, a = (slot >> 3) & 127, ch = slot >> 10;
                const float4* p = (const float4*)(in + (size_t)ch * NSTATE + ncb + a * 128 + nlh * 64 + c * 8);
                stg[2 * s] = p[0];
                stg[2 * s + 1] = p[1];
            }
        }

        float acc0[2][4], acc1[2][4];
        #pragma unroll
        for (int j = 0; j < 2; ++j)
            #pragma unroll
            for (int q = 0; q < 4; ++q) { acc0[j][q] = 0.f; acc1[j][q] = 0.f; }

        const uint32_t bbuf = sb + BH_OFF + buf * 65536u;

        uint32_t af[2][4][4], bfr[2][4][4];
        {
            const uint32_t aa = abase + (uint32_t)((acl ^ ar7) << 4);
            LDM4(af[0][0], aa);
            LDM4(af[0][1], aa + 16384);
            LDM4(af[0][2], aa + 32768);
            LDM4(af[0][3], aa + 49152);
            const int row = br_off;
            const uint32_t ba = bbuf + (uint32_t)row * 128u
                              + (uint32_t)((cidx ^ (row & 7)) << 4);
            LDM4T(bfr[0][0], ba);
            LDM4T(bfr[0][1], ba + 16384);
            LDM4T(bfr[0][2], ba + 32768);
            LDM4T(bfr[0][3], ba + 49152);
        }

        #pragma unroll
        for (int ks = 0; ks < 8; ++ks) {
            const int cur = ks & 1, nxt = cur ^ 1;
            if (ks < 7) {
                const uint32_t aa = abase + (uint32_t)((((ks + 1) * 2 + acl) ^ ar7) << 4);
                LDM4(af[nxt][0], aa);
                LDM4(af[nxt][1], aa + 16384);
                LDM4(af[nxt][2], aa + 32768);
                LDM4(af[nxt][3], aa + 49152);
                const int row = (ks + 1) * 16 + br_off;
                const uint32_t ba = bbuf + (uint32_t)row * 128u
                                  + (uint32_t)((cidx ^ (row & 7)) << 4);
                LDM4T(bfr[nxt][0], ba);
                LDM4T(bfr[nxt][1], ba + 16384);
                LDM4T(bfr[nxt][2], ba + 32768);
                LDM4T(bfr[nxt][3], ba + 49152);
            }
            uint32_t naf2[4], naf3[4];
            #pragma unroll
            for (int q = 0; q < 4; ++q) {
                naf2[q] = af[cur][2][q] ^ SGN;
                naf3[q] = af[cur][3][q] ^ SGN;
            }
            MMA12P(acc0[0], acc1[0], af[cur], naf2, naf3, bfr[cur], 0)
            MMA12P(acc0[1], acc1[1], af[cur], naf2, naf3, bfr[cur], 1)
        }

        if (hasnext) {
            #pragma unroll
            for (int s = 0; s < 2; ++s) {
                const int slot = t + 512 * s;
                const int c = slot & 7, a = (slot >> 3) & 127, ch = slot >> 10;
                uint4 hi, lo;
                cvt8(stg[2 * s], stg[2 * s + 1], &hi, &lo);
                char* wp = smem + BH_OFF + (buf ^ 1u) * 65536u + (ch * 2) * 16384 + a * 128
                         + ((c ^ (a & 7)) * 16);
                *(uint4*)wp = hi;
                *(uint4*)(wp + 16384) = lo;
            }
            #pragma unroll
            for (int s = 2; s < 4; ++s) {
                const int slot = t + 512 * s;
                const int c = slot & 7, a = (slot >> 3) & 127, ch = slot >> 10;
                const float4* p = (const float4*)(in + (size_t)ch * NSTATE + ncb + a * 128 + nlh * 64 + c * 8);
                uint4 hi, lo;
                cvt8(p[0], p[1], &hi, &lo);
                char* wp = smem + BH_OFF + (buf ^ 1u) * 65536u + (ch * 2) * 16384 + a * 128
                         + ((c ^ (a & 7)) * 16);
                *(uint4*)wp = hi;
                *(uint4*)(wp + 16384) = lo;
            }
        }

        {
            const size_t row0 = (size_t)khalf * 64 + mrow0 + rg;
            float* o0 = out + cb;
            float* o1 = out + NSTATE + cb;
            #pragma unroll
            for (int j = 0; j < 2; ++j) {
                const int n = lh * 64 + ncol0 + j * 8 + tg * 2;
                *(float2*)(o0 + row0 * 128 + n)       = make_float2(acc0[j][0], acc0[j][1]);
                *(float2*)(o0 + (row0 + 8) * 128 + n) = make_float2(acc0[j][2], acc0[j][3]);
                *(float2*)(o1 + row0 * 128 + n)       = make_float2(acc1[j][0], acc1[j][1]);
                *(float2*)(o1 + (row0 + 8) * 128 + n) = make_float2(acc1[j][2], acc1[j][3]);
            }
        }
        __syncthreads();
        buf ^= 1u;
    }
}

// ---------------------------------------------------------------------------
extern "C" void kernel_launch(void* const* d_in, const int* in_sizes, int n_in,
                              void* d_out, int out_size)
{
    const float* state = (const float*)d_in[0];
    const float* U     = (const float*)d_in[1];
    if (n_in >= 2 && in_sizes[0] < in_sizes[1]) {
        const float* tmp = state; state = U; U = tmp;
    }
    float* out = (float*)d_out;

    float* scratch = nullptr;
    cudaGetSymbolAddress((void**)&scratch, g_scratch);
    __nv_bfloat16* ubf = nullptr;
    cudaGetSymbolAddress((void**)&ubf, g_ubf);

    cudaFuncSetAttribute(gate_lowp,  cudaFuncAttributeMaxDynamicSharedMemorySize, (int)SMEM_BYTES);
    cudaFuncSetAttribute(gate_highp, cudaFuncAttributeMaxDynamicSharedMemorySize, (int)SMEM_BYTES);

    prep_u<<<512, 256>>>(U);
    gate_lowp<<<148, 512, SMEM_BYTES>>>(state,   scratch, ubf);            // gate 0
    gate_lowp<<<148, 512, SMEM_BYTES>>>(scratch, out,     ubf + 65536);    // gate 1
    gate_lowp<<<148, 512, SMEM_BYTES>>>(out,     scratch, ubf + 131072);   // gate 2
    gate_highp<<<148, 512, SMEM_BYTES>>>(scratch, out,    ubf + 196608);   // gate 3
}

// round 12
// speedup vs baseline: 1.0599x; 1.0280x over previous
#include <cuda_runtime.h>
#include <cuda_bf16.h>
#include <cstdint>

#define NSTATE (1u << 23)

__device__ float g_scratch[1u << 24];
__device__ __nv_bfloat16 g_ubf[262144];   // 4 gates x 4 matrices x 16384 bf16

#define SMEM_BYTES 196608u
#define SGN 0x80008000u

// gates 0-2 (team kernel): U tiles [0,131072); team buffers at 131072 + team*32768 + buf*16384
// gate 3: U-half tiles [0,65536), state B buffers 65536 + buf*65536 (4 x 16384)
#define BH_OFF 65536u

__device__ __forceinline__ uint32_t smem_u32(const void* p) {
    uint32_t a;
    asm("{ .reg .u64 t; cvta.to.shared.u64 t, %1; cvt.u32.u64 %0, t; }" : "=r"(a) : "l"(p));
    return a;
}

#define CPASYNC16(saddr, gptr)                                                  \
    asm volatile("cp.async.cg.shared.global [%0], [%1], 16;"                    \
        :: "r"(saddr), "l"(gptr) : "memory")

#define LDM4(r, addr)                                                           \
    asm volatile("ldmatrix.sync.aligned.m8n8.x4.shared.b16 {%0,%1,%2,%3}, [%4];"\
        : "=r"((r)[0]), "=r"((r)[1]), "=r"((r)[2]), "=r"((r)[3]) : "r"(addr))

#define LDM4T(r, addr)                                                          \
    asm volatile("ldmatrix.sync.aligned.m8n8.x4.trans.shared.b16 {%0,%1,%2,%3}, [%4];"\
        : "=r"((r)[0]), "=r"((r)[1]), "=r"((r)[2]), "=r"((r)[3]) : "r"(addr))

#define MMA(C, A, b0v, b1v)                                                     \
    asm volatile("mma.sync.aligned.m16n8k16.row.col.f32.bf16.bf16.f32 "         \
        "{%0,%1,%2,%3}, {%4,%5,%6,%7}, {%8,%9}, {%0,%1,%2,%3};"                 \
        : "+f"((C)[0]), "+f"((C)[1]), "+f"((C)[2]), "+f"((C)[3])                \
        : "r"((A)[0]), "r"((A)[1]), "r"((A)[2]), "r"((A)[3]), "r"(b0v), "r"(b1v))

// 12-MMA block: ch1 = A_r*B_r - A_i*B_i ; ch0 = A_i*B_r + A_r*B_i (hi*hi+hi*lo+lo*hi)
#define MMA12(A0, J2)                                                           \
    MMA(acc1[A0], af[0], bf[0][J2], bf[0][(J2) + 2]);                           \
    MMA(acc1[A0], af[0], bf[1][J2], bf[1][(J2) + 2]);                           \
    MMA(acc1[A0], af[1], bf[0][J2], bf[0][(J2) + 2]);                           \
    MMA(acc1[A0], naf2,  bf[2][J2], bf[2][(J2) + 2]);                           \
    MMA(acc1[A0], naf2,  bf[3][J2], bf[3][(J2) + 2]);                           \
    MMA(acc1[A0], naf3,  bf[2][J2], bf[2][(J2) + 2]);                           \
    MMA(acc0[A0], af[2], bf[0][J2], bf[0][(J2) + 2]);                           \
    MMA(acc0[A0], af[2], bf[1][J2], bf[1][(J2) + 2]);                           \
    MMA(acc0[A0], af[3], bf[0][J2], bf[0][(J2) + 2]);                           \
    MMA(acc0[A0], af[0], bf[2][J2], bf[2][(J2) + 2]);                           \
    MMA(acc0[A0], af[0], bf[3][J2], bf[3][(J2) + 2]);                           \
    MMA(acc0[A0], af[1], bf[2][J2], bf[2][(J2) + 2]);

// fp32 x8 -> bf16 hi (16B) + bf16 lo (16B)
__device__ __forceinline__ void cvt8(float4 x, float4 y, uint4* hi, uint4* lo) {
    float f[8] = {x.x, x.y, x.z, x.w, y.x, y.y, y.z, y.w};
    uint32_t h[8], l[8];
    #pragma unroll
    for (int i = 0; i < 8; ++i) {
        __nv_bfloat16 hb = __float2bfloat16(f[i]);
        h[i] = (uint32_t)__bfloat16_as_ushort(hb);
        l[i] = (uint32_t)__bfloat16_as_ushort(__float2bfloat16(f[i] - __bfloat162float(hb)));
    }
    *hi = make_uint4(h[0] | (h[1] << 16), h[2] | (h[3] << 16),
                     h[4] | (h[5] << 16), h[6] | (h[7] << 16));
    *lo = make_uint4(l[0] | (l[1] << 16), l[2] | (l[3] << 16),
                     l[4] | (l[5] << 16), l[6] | (l[7] << 16));
}

// ---------------------------------------------------------------------------
__global__ void prep_u(const float* __restrict__ U)
{
    const int i = blockIdx.x * 256 + threadIdx.x;   // 131072
    const int a = i & 127, k = (i >> 7) & 127, c = (i >> 14) & 1, g = i >> 15;
    const float x = U[i];
    const __nv_bfloat16 hi = __float2bfloat16(x);
    const __nv_bfloat16 lo = __float2bfloat16(x - __bfloat162float(hi));
    const int h = k * 128 + (((a >> 3) ^ (k & 7)) << 3) + (a & 7);
    g_ubf[g * 65536 + (c * 2 + 0) * 16384 + h] = hi;
    g_ubf[g * 65536 + (c * 2 + 1) * 16384 + h] = lo;
}

// ---------------------------------------------------------------------------
// Gates 0-2: 512 threads split into TWO independent 8-warp teams.
// Team k (warps 8k..8k+7) processes 16-row items (stream id = bid*2+k, stride 296)
// with its own double-buffered state tiles and its own named barrier -> the
// teams run anti-phase: one team's MMA covers the other's convert/epilogue.
__global__ void __launch_bounds__(512, 1)
gate_lowt(const float* __restrict__ in, float* __restrict__ out,
          const __nv_bfloat16* __restrict__ img)
{
    extern __shared__ char smem[];
    const uint32_t sb = smem_u32(smem);
    const int t = threadIdx.x, lane = t & 31, w = t >> 5;
    const int team = w >> 3;             // 0/1
    const int tw = w & 7;                // n-group within team
    const int tt = t & 255;              // thread id within team

    // stage U image once (128KB, pre-swizzled)
    {
        const uint4* src = (const uint4*)img;
        #pragma unroll
        for (int j = 0; j < 16; ++j) {
            const int idx = t + 512 * j;
            CPASYNC16(sb + (uint32_t)idx * 16u, src + idx);
        }
        asm volatile("cp.async.commit_group;" ::: "memory");
    }

    const uint32_t tb0 = 131072u + (uint32_t)team * 32768u;

    int item = blockIdx.x * 2 + team;     // 4096 items of 16 rows
    // first item convert into team buf 0 (512 slots per team, 2 per thread)
    {
        const size_t base = (size_t)item * 2048;
        #pragma unroll
        for (int s = 0; s < 2; ++s) {
            const int slot = tt + 256 * s;
            const int c = slot & 15, r = (slot >> 4) & 15, ch = slot >> 8;
            const float4* p = (const float4*)(in + (size_t)ch * NSTATE + base + r * 128 + c * 8);
            uint4 hi, lo;
            cvt8(p[0], p[1], &hi, &lo);
            char* wp = smem + tb0 + (ch * 2) * 4096 + r * 256 + ((c ^ (r & 7)) * 16);
            *(uint4*)wp = hi;
            *(uint4*)(wp + 4096) = lo;
        }
    }
    asm volatile("cp.async.wait_group 0;" ::: "memory");
    __syncthreads();                      // U + both teams' first buffers ready

    const int ncol0 = tw * 16;
    const int ar = lane & 15, acl = lane >> 4, ar7 = ar & 7;
    const int br_off = lane & 15, bcl = lane >> 4;
    const int rg = lane >> 2, tg = lane & 3;
    const int brow = ncol0 + br_off;
    const uint32_t bbase = sb + (uint32_t)brow * 256u;
    const int br7 = brow & 7;
    const int barid = 1 + team;

    uint32_t buf = 0;
    for (; item < 4096; item += 296) {
        const int next = item + 296;
        const bool hasnext = next < 4096;
        float4 stg[4];
        if (hasnext) {
            const size_t base = (size_t)next * 2048;
            #pragma unroll
            for (int s = 0; s < 2; ++s) {
                const int slot = tt + 256 * s;
                const int c = slot & 15, r = (slot >> 4) & 15, ch = slot >> 8;
                const float4* p = (const float4*)(in + (size_t)ch * NSTATE + base + r * 128 + c * 8);
                stg[2 * s] = p[0];
                stg[2 * s + 1] = p[1];
            }
        }

        float acc0[2][4], acc1[2][4];
        #pragma unroll
        for (int j = 0; j < 2; ++j)
            #pragma unroll
            for (int q = 0; q < 4; ++q) { acc0[j][q] = 0.f; acc1[j][q] = 0.f; }

        const uint32_t abase = sb + tb0 + buf * 16384u + (uint32_t)ar * 256u;
        #pragma unroll 1
        for (int ks = 0; ks < 8; ++ks) {
            uint32_t af[4][4], naf2[4], naf3[4];
            const uint32_t aa = abase + (uint32_t)(((ks * 2 + acl) ^ ar7) << 4);
            LDM4(af[0], aa);
            LDM4(af[1], aa + 4096);
            LDM4(af[2], aa + 8192);
            LDM4(af[3], aa + 12288);
            #pragma unroll
            for (int q = 0; q < 4; ++q) { naf2[q] = af[2][q] ^ SGN; naf3[q] = af[3][q] ^ SGN; }

            uint32_t bf[4][4];
            const uint32_t ba = bbase + (uint32_t)(((ks * 2 + bcl) ^ br7) << 4);
            LDM4(bf[0], ba);
            LDM4(bf[1], ba + 32768);
            LDM4(bf[2], ba + 65536);
            LDM4(bf[3], ba + 98304);
            MMA12(0, 0)
            MMA12(1, 1)
        }

        if (hasnext) {
            #pragma unroll
            for (int s = 0; s < 2; ++s) {
                const int slot = tt + 256 * s;
                const int c = slot & 15, r = (slot >> 4) & 15, ch = slot >> 8;
                uint4 hi, lo;
                cvt8(stg[2 * s], stg[2 * s + 1], &hi, &lo);
                char* wp = smem + tb0 + (buf ^ 1u) * 16384u + (ch * 2) * 4096 + r * 256
                         + ((c ^ (r & 7)) * 16);
                *(uint4*)wp = hi;
                *(uint4*)(wp + 4096) = lo;
            }
        }

        {
            const size_t row0 = (size_t)item * 16 + rg;
            float* o0 = out;
            float* o1 = out + NSTATE;
            #pragma unroll
            for (int j = 0; j < 2; ++j) {
                const int n = ncol0 + j * 8 + tg * 2;
                *(float2*)(o0 + row0 * 128 + n)       = make_float2(acc0[j][0], acc0[j][1]);
                *(float2*)(o0 + (row0 + 8) * 128 + n) = make_float2(acc0[j][2], acc0[j][3]);
                *(float2*)(o1 + row0 * 128 + n)       = make_float2(acc1[j][0], acc1[j][1]);
                *(float2*)(o1 + (row0 + 8) * 128 + n) = make_float2(acc1[j][2], acc1[j][3]);
            }
        }
        asm volatile("bar.sync %0, %1;" :: "r"(barid), "r"(256) : "memory");
        buf ^= 1u;
    }
}

// ---------------------------------------------------------------------------
// Gate 3 (R9 version, unchanged): persistent 512 threads; A = U k-half resident.
__global__ void __launch_bounds__(512, 1)
gate_highp(const float* __restrict__ in, float* __restrict__ out,
           const __nv_bfloat16* __restrict__ img)
{
    extern __shared__ char smem[];
    const uint32_t sb = smem_u32(smem);
    const int t = threadIdx.x, lane = t & 31, w = t >> 5;
    const int khalf = blockIdx.x & 1;
    const int pairid = blockIdx.x >> 1;   // 0..73

    {
        const uint4* src = (const uint4*)img;
        #pragma unroll
        for (int j = 0; j < 8; ++j) {
            const int idx = t + 512 * j;              // 0..4095
            const int m = idx >> 10, within = idx & 1023;
            CPASYNC16(sb + (uint32_t)idx * 16u, src + m * 2048 + khalf * 1024 + within);
        }
        asm volatile("cp.async.commit_group;" ::: "memory");
    }

    int widx = pairid;                    // 1024 = 512 chunks x 2 l-halves
    {
        const int chunk = widx >> 1, lh = widx & 1;
        const size_t cb = (size_t)chunk * 16384;
        #pragma unroll
        for (int s = 0; s < 4; ++s) {
            const int slot = t + 512 * s;
            const int c = slot & 7, a = (slot >> 3) & 127, ch = slot >> 10;
            const float4* p = (const float4*)(in + (size_t)ch * NSTATE + cb + a * 128 + lh * 64 + c * 8);
            uint4 hi, lo;
            cvt8(p[0], p[1], &hi, &lo);
            char* wp = smem + BH_OFF + (ch * 2) * 16384 + a * 128 + ((c ^ (a & 7)) * 16);
            *(uint4*)wp = hi;
            *(uint4*)(wp + 16384) = lo;
        }
    }
    asm volatile("cp.async.wait_group 0;" ::: "memory");
    __syncthreads();

    const int mrow0 = (w & 3) * 16, ncol0 = (w >> 2) * 16;
    const int ar = mrow0 + (lane & 15), acl = lane >> 4, ar7 = ar & 7;
    const int br_off = (lane & 7) + ((lane & 16) >> 1), bcl = (lane >> 3) & 1;
    const int rg = lane >> 2, tg = lane & 3;
    const uint32_t abase = sb + (uint32_t)ar * 256u;
    const int cidx = (ncol0 >> 3) + bcl;

    uint32_t buf = 0;
    for (; widx < 1024; widx += 74) {
        const int chunk = widx >> 1, lh = widx & 1;
        const size_t cb = (size_t)chunk * 16384;
        const int nwidx = widx + 74;
        const bool hasnext = nwidx < 1024;
        const int nchunk = nwidx >> 1, nlh = nwidx & 1;
        const size_t ncb = (size_t)nchunk * 16384;

        float4 stg[4];
        if (hasnext) {
            #pragma unroll
            for (int s = 0; s < 2; ++s) {
                const int slot = t + 512 * s;
                const int c = slot & 7, a = (slot >> 3) & 127, ch = slot >> 10;
                const float4* p = (const float4*)(in + (size_t)ch * NSTATE + ncb + a * 128 + nlh * 64 + c * 8);
                stg[2 * s] = p[0];
                stg[2 * s + 1] = p[1];
            }
        }

        float acc0[2][4], acc1[2][4];
        #pragma unroll
        for (int j = 0; j < 2; ++j)
            #pragma unroll
            for (int q = 0; q < 4; ++q) { acc0[j][q] = 0.f; acc1[j][q] = 0.f; }

        const uint32_t bbuf = sb + BH_OFF + buf * 65536u;
        #pragma unroll 1
        for (int ks = 0; ks < 8; ++ks) {
            uint32_t af[4][4], naf2[4], naf3[4];
            const uint32_t aa = abase + (uint32_t)(((ks * 2 + acl) ^ ar7) << 4);
            LDM4(af[0], aa);
            LDM4(af[1], aa + 16384);
            LDM4(af[2], aa + 32768);
            LDM4(af[3], aa + 49152);
            #pragma unroll
            for (int q = 0; q < 4; ++q) { naf2[q] = af[2][q] ^ SGN; naf3[q] = af[3][q] ^ SGN; }

            uint32_t bf[4][4];
            const int row = ks * 16 + br_off;
            const uint32_t ba = bbuf + (uint32_t)row * 128u
                              + (uint32_t)((cidx ^ (row & 7)) << 4);
            LDM4T(bf[0], ba);
            LDM4T(bf[1], ba + 16384);
            LDM4T(bf[2], ba + 32768);
            LDM4T(bf[3], ba + 49152);
            MMA12(0, 0)
            MMA12(1, 1)
        }

        if (hasnext) {
            #pragma unroll
            for (int s = 0; s < 2; ++s) {
                const int slot = t + 512 * s;
                const int c = slot & 7, a = (slot >> 3) & 127, ch = slot >> 10;
                uint4 hi, lo;
                cvt8(stg[2 * s], stg[2 * s + 1], &hi, &lo);
                char* wp = smem + BH_OFF + (buf ^ 1u) * 65536u + (ch * 2) * 16384 + a * 128
                         + ((c ^ (a & 7)) * 16);
                *(uint4*)wp = hi;
                *(uint4*)(wp + 16384) = lo;
            }
            #pragma unroll
            for (int s = 2; s < 4; ++s) {
                const int slot = t + 512 * s;
                const int c = slot & 7, a = (slot >> 3) & 127, ch = slot >> 10;
                const float4* p = (const float4*)(in + (size_t)ch * NSTATE + ncb + a * 128 + nlh * 64 + c * 8);
                uint4 hi, lo;
                cvt8(p[0], p[1], &hi, &lo);
                char* wp = smem + BH_OFF + (buf ^ 1u) * 65536u + (ch * 2) * 16384 + a * 128
                         + ((c ^ (a & 7)) * 16);
                *(uint4*)wp = hi;
                *(uint4*)(wp + 16384) = lo;
            }
        }

        {
            const size_t row0 = (size_t)khalf * 64 + mrow0 + rg;
            float* o0 = out + cb;
            float* o1 = out + NSTATE + cb;
            #pragma unroll
            for (int j = 0; j < 2; ++j) {
                const int n = lh * 64 + ncol0 + j * 8 + tg * 2;
                *(float2*)(o0 + row0 * 128 + n)       = make_float2(acc0[j][0], acc0[j][1]);
                *(float2*)(o0 + (row0 + 8) * 128 + n) = make_float2(acc0[j][2], acc0[j][3]);
                *(float2*)(o1 + row0 * 128 + n)       = make_float2(acc1[j][0], acc1[j][1]);
                *(float2*)(o1 + (row0 + 8) * 128 + n) = make_float2(acc1[j][2], acc1[j][3]);
            }
        }
        __syncthreads();
        buf ^= 1u;
    }
}

// ---------------------------------------------------------------------------
extern "C" void kernel_launch(void* const* d_in, const int* in_sizes, int n_in,
                              void* d_out, int out_size)
{
    const float* state = (const float*)d_in[0];
    const float* U     = (const float*)d_in[1];
    if (n_in >= 2 && in_sizes[0] < in_sizes[1]) {
        const float* tmp = state; state = U; U = tmp;
    }
    float* out = (float*)d_out;

    float* scratch = nullptr;
    cudaGetSymbolAddress((void**)&scratch, g_scratch);
    __nv_bfloat16* ubf = nullptr;
    cudaGetSymbolAddress((void**)&ubf, g_ubf);

    cudaFuncSetAttribute(gate_lowt,  cudaFuncAttributeMaxDynamicSharedMemorySize, (int)SMEM_BYTES);
    cudaFuncSetAttribute(gate_highp, cudaFuncAttributeMaxDynamicSharedMemorySize, (int)SMEM_BYTES);

    prep_u<<<512, 256>>>(U);
    gate_lowt<<<148, 512, SMEM_BYTES>>>(state,   scratch, ubf);            // gate 0
    gate_lowt<<<148, 512, SMEM_BYTES>>>(scratch, out,     ubf + 65536);    // gate 1
    gate_lowt<<<148, 512, SMEM_BYTES>>>(out,     scratch, ubf + 131072);   // gate 2
    gate_highp<<<148, 512, SMEM_BYTES>>>(scratch, out,    ubf + 196608);   // gate 3
}

// round 13
// speedup vs baseline: 1.0828x; 1.0216x over previous
#include <cuda_runtime.h>
#include <cuda_bf16.h>
#include <cstdint>

#define NSTATE (1u << 23)

__device__ float g_scratch[1u << 24];
__device__ __nv_bfloat16 g_ubf[262144];   // 4 gates x 4 matrices x 16384 bf16

#define SMEM_BYTES_LO 163840u   // U image 128KB + 2 x 16KB state buffers
#define SMEM_BYTES_HI 196608u   // gate 3 (unchanged)
#define SGN 0x80008000u

#define AL_OFF 131072u          // gates 0-2 state buffers
#define BH_OFF 65536u           // gate 3 state buffers

__device__ __forceinline__ uint32_t smem_u32(const void* p) {
    uint32_t a;
    asm("{ .reg .u64 t; cvta.to.shared.u64 t, %1; cvt.u32.u64 %0, t; }" : "=r"(a) : "l"(p));
    return a;
}

#define CPASYNC16(saddr, gptr)                                                  \
    asm volatile("cp.async.cg.shared.global [%0], [%1], 16;"                    \
        :: "r"(saddr), "l"(gptr) : "memory")

#define LDM4(r, addr)                                                           \
    asm volatile("ldmatrix.sync.aligned.m8n8.x4.shared.b16 {%0,%1,%2,%3}, [%4];"\
        : "=r"((r)[0]), "=r"((r)[1]), "=r"((r)[2]), "=r"((r)[3]) : "r"(addr))

#define LDM4T(r, addr)                                                          \
    asm volatile("ldmatrix.sync.aligned.m8n8.x4.trans.shared.b16 {%0,%1,%2,%3}, [%4];"\
        : "=r"((r)[0]), "=r"((r)[1]), "=r"((r)[2]), "=r"((r)[3]) : "r"(addr))

#define MMA(C, A, b0v, b1v)                                                     \
    asm volatile("mma.sync.aligned.m16n8k16.row.col.f32.bf16.bf16.f32 "         \
        "{%0,%1,%2,%3}, {%4,%5,%6,%7}, {%8,%9}, {%0,%1,%2,%3};"                 \
        : "+f"((C)[0]), "+f"((C)[1]), "+f"((C)[2]), "+f"((C)[3])                \
        : "r"((A)[0]), "r"((A)[1]), "r"((A)[2]), "r"((A)[3]), "r"(b0v), "r"(b1v))

// 12-MMA block on explicit fragment sets:
// ch1 = A_r*B_r - A_i*B_i ; ch0 = A_i*B_r + A_r*B_i (hi*hi + hi*lo + lo*hi each)
#define MMA12P(ACC0, ACC1, AF, N2, N3, BF, J2)                                  \
    MMA(ACC1, AF[0], BF[0][J2], BF[0][(J2) + 2]);                               \
    MMA(ACC1, AF[0], BF[1][J2], BF[1][(J2) + 2]);                               \
    MMA(ACC1, AF[1], BF[0][J2], BF[0][(J2) + 2]);                               \
    MMA(ACC1, N2,    BF[2][J2], BF[2][(J2) + 2]);                               \
    MMA(ACC1, N2,    BF[3][J2], BF[3][(J2) + 2]);                               \
    MMA(ACC1, N3,    BF[2][J2], BF[2][(J2) + 2]);                               \
    MMA(ACC0, AF[2], BF[0][J2], BF[0][(J2) + 2]);                               \
    MMA(ACC0, AF[2], BF[1][J2], BF[1][(J2) + 2]);                               \
    MMA(ACC0, AF[3], BF[0][J2], BF[0][(J2) + 2]);                               \
    MMA(ACC0, AF[0], BF[2][J2], BF[2][(J2) + 2]);                               \
    MMA(ACC0, AF[0], BF[3][J2], BF[3][(J2) + 2]);                               \
    MMA(ACC0, AF[1], BF[2][J2], BF[2][(J2) + 2]);

// fp32 x8 -> bf16 hi (16B) + bf16 lo (16B)
__device__ __forceinline__ void cvt8(float4 x, float4 y, uint4* hi, uint4* lo) {
    float f[8] = {x.x, x.y, x.z, x.w, y.x, y.y, y.z, y.w};
    uint32_t h[8], l[8];
    #pragma unroll
    for (int i = 0; i < 8; ++i) {
        __nv_bfloat16 hb = __float2bfloat16(f[i]);
        h[i] = (uint32_t)__bfloat16_as_ushort(hb);
        l[i] = (uint32_t)__bfloat16_as_ushort(__float2bfloat16(f[i] - __bfloat162float(hb)));
    }
    *hi = make_uint4(h[0] | (h[1] << 16), h[2] | (h[3] << 16),
                     h[4] | (h[5] << 16), h[6] | (h[7] << 16));
    *lo = make_uint4(l[0] | (l[1] << 16), l[2] | (l[3] << 16),
                     l[4] | (l[5] << 16), l[6] | (l[7] << 16));
}

// ---------------------------------------------------------------------------
__global__ void prep_u(const float* __restrict__ U)
{
    const int i = blockIdx.x * 256 + threadIdx.x;   // 131072
    const int a = i & 127, k = (i >> 7) & 127, c = (i >> 14) & 1, g = i >> 15;
    const float x = U[i];
    const __nv_bfloat16 hi = __float2bfloat16(x);
    const __nv_bfloat16 lo = __float2bfloat16(x - __bfloat162float(hi));
    const int h = k * 128 + (((a >> 3) ^ (k & 7)) << 3) + (a & 7);
    g_ubf[g * 65536 + (c * 2 + 0) * 16384 + h] = hi;
    g_ubf[g * 65536 + (c * 2 + 1) * 16384 + h] = lo;
}

// ---------------------------------------------------------------------------
// Gates 0-2, REGISTER-RESIDENT U: 256 threads, 8 warps x 16 output cols.
// Each warp loads its 128 U-fragment registers ONCE; the per-item mainloop
// issues only the 4 A-side ldmatrix per ks (SMEM crossbar traffic /4).
__global__ void __launch_bounds__(256, 1)
gate_lowr(const float* __restrict__ in, float* __restrict__ out,
          const __nv_bfloat16* __restrict__ img)
{
    extern __shared__ char smem[];
    const uint32_t sb = smem_u32(smem);
    const int t = threadIdx.x, lane = t & 31, w = t >> 5;

    // stage U image once (128KB, pre-swizzled)
    {
        const uint4* src = (const uint4*)img;
        #pragma unroll
        for (int j = 0; j < 32; ++j) {
            const int idx = t + 256 * j;
            CPASYNC16(sb + (uint32_t)idx * 16u, src + idx);
        }
        asm volatile("cp.async.commit_group;" ::: "memory");
    }

    int item = blockIdx.x;
    // first item convert into buf 0 (512 slots, 2 per thread)
    {
        const size_t base = (size_t)item * 2048;
        #pragma unroll
        for (int s = 0; s < 2; ++s) {
            const int slot = t + 256 * s;
            const int c = slot & 15, r = (slot >> 4) & 15, ch = slot >> 8;
            const float4* p = (const float4*)(in + (size_t)ch * NSTATE + base + r * 128 + c * 8);
            uint4 hi, lo;
            cvt8(p[0], p[1], &hi, &lo);
            char* wp = smem + AL_OFF + (ch * 2) * 4096 + r * 256 + ((c ^ (r & 7)) * 16);
            *(uint4*)wp = hi;
            *(uint4*)(wp + 4096) = lo;
        }
    }
    asm volatile("cp.async.wait_group 0;" ::: "memory");
    __syncthreads();

    const int ncol0 = w * 16;
    const int ar = lane & 15, acl = lane >> 4, ar7 = ar & 7;
    const int brow = ncol0 + (lane & 15), bcl = lane >> 4;
    const uint32_t bbase = sb + (uint32_t)brow * 256u;
    const int br7 = brow & 7;
    const int rg = lane >> 2, tg = lane & 3;

    // Load this warp's U fragments ONCE (128 registers).
    uint32_t uf[8][4][4];
    #pragma unroll
    for (int ks = 0; ks < 8; ++ks) {
        const uint32_t ba = bbase + (uint32_t)(((ks * 2 + bcl) ^ br7) << 4);
        LDM4(uf[ks][0], ba);
        LDM4(uf[ks][1], ba + 32768);
        LDM4(uf[ks][2], ba + 65536);
        LDM4(uf[ks][3], ba + 98304);
    }

    uint32_t buf = 0;
    for (; item < 4096; item += 148) {
        const int next = item + 148;
        const bool hasnext = next < 4096;
        float4 stg[4];
        if (hasnext) {
            const size_t base = (size_t)next * 2048;
            #pragma unroll
            for (int s = 0; s < 2; ++s) {
                const int slot = t + 256 * s;
                const int c = slot & 15, r = (slot >> 4) & 15, ch = slot >> 8;
                const float4* p = (const float4*)(in + (size_t)ch * NSTATE + base + r * 128 + c * 8);
                stg[2 * s] = p[0];
                stg[2 * s + 1] = p[1];
            }
        }

        float acc0[2][4], acc1[2][4];
        #pragma unroll
        for (int j = 0; j < 2; ++j)
            #pragma unroll
            for (int q = 0; q < 4; ++q) { acc0[j][q] = 0.f; acc1[j][q] = 0.f; }

        const uint32_t abase = sb + AL_OFF + buf * 16384u + (uint32_t)ar * 256u;
        #pragma unroll
        for (int ks = 0; ks < 8; ++ks) {
            uint32_t af[4][4], naf2[4], naf3[4];
            const uint32_t aa = abase + (uint32_t)(((ks * 2 + acl) ^ ar7) << 4);
            LDM4(af[0], aa);              // Sr_hi
            LDM4(af[1], aa + 4096);       // Sr_lo
            LDM4(af[2], aa + 8192);       // Si_hi
            LDM4(af[3], aa + 12288);      // Si_lo
            #pragma unroll
            for (int q = 0; q < 4; ++q) { naf2[q] = af[2][q] ^ SGN; naf3[q] = af[3][q] ^ SGN; }

            MMA12P(acc0[0], acc1[0], af, naf2, naf3, uf[ks], 0)
            MMA12P(acc0[1], acc1[1], af, naf2, naf3, uf[ks], 1)
        }

        if (hasnext) {
            #pragma unroll
            for (int s = 0; s < 2; ++s) {
                const int slot = t + 256 * s;
                const int c = slot & 15, r = (slot >> 4) & 15, ch = slot >> 8;
                uint4 hi, lo;
                cvt8(stg[2 * s], stg[2 * s + 1], &hi, &lo);
                char* wp = smem + AL_OFF + (buf ^ 1u) * 16384u + (ch * 2) * 4096 + r * 256
                         + ((c ^ (r & 7)) * 16);
                *(uint4*)wp = hi;
                *(uint4*)(wp + 4096) = lo;
            }
        }

        {
            const size_t row0 = (size_t)item * 16 + rg;
            float* o0 = out;
            float* o1 = out + NSTATE;
            #pragma unroll
            for (int j = 0; j < 2; ++j) {
                const int n = ncol0 + j * 8 + tg * 2;
                *(float2*)(o0 + row0 * 128 + n)       = make_float2(acc0[j][0], acc0[j][1]);
                *(float2*)(o0 + (row0 + 8) * 128 + n) = make_float2(acc0[j][2], acc0[j][3]);
                *(float2*)(o1 + row0 * 128 + n)       = make_float2(acc1[j][0], acc1[j][1]);
                *(float2*)(o1 + (row0 + 8) * 128 + n) = make_float2(acc1[j][2], acc1[j][3]);
            }
        }
        __syncthreads();
        buf ^= 1u;
    }
}

// ---------------------------------------------------------------------------
// Gate 3 (unchanged R12): persistent 512 threads; A = U k-half resident in SMEM.
__global__ void __launch_bounds__(512, 1)
gate_highp(const float* __restrict__ in, float* __restrict__ out,
           const __nv_bfloat16* __restrict__ img)
{
    extern __shared__ char smem[];
    const uint32_t sb = smem_u32(smem);
    const int t = threadIdx.x, lane = t & 31, w = t >> 5;
    const int khalf = blockIdx.x & 1;
    const int pairid = blockIdx.x >> 1;   // 0..73

    {
        const uint4* src = (const uint4*)img;
        #pragma unroll
        for (int j = 0; j < 8; ++j) {
            const int idx = t + 512 * j;              // 0..4095
            const int m = idx >> 10, within = idx & 1023;
            CPASYNC16(sb + (uint32_t)idx * 16u, src + m * 2048 + khalf * 1024 + within);
        }
        asm volatile("cp.async.commit_group;" ::: "memory");
    }

    int widx = pairid;                    // 1024 = 512 chunks x 2 l-halves
    {
        const int chunk = widx >> 1, lh = widx & 1;
        const size_t cb = (size_t)chunk * 16384;
        #pragma unroll
        for (int s = 0; s < 4; ++s) {
            const int slot = t + 512 * s;
            const int c = slot & 7, a = (slot >> 3) & 127, ch = slot >> 10;
            const float4* p = (const float4*)(in + (size_t)ch * NSTATE + cb + a * 128 + lh * 64 + c * 8);
            uint4 hi, lo;
            cvt8(p[0], p[1], &hi, &lo);
            char* wp = smem + BH_OFF + (ch * 2) * 16384 + a * 128 + ((c ^ (a & 7)) * 16);
            *(uint4*)wp = hi;
            *(uint4*)(wp + 16384) = lo;
        }
    }
    asm volatile("cp.async.wait_group 0;" ::: "memory");
    __syncthreads();

    const int mrow0 = (w & 3) * 16, ncol0 = (w >> 2) * 16;
    const int ar = mrow0 + (lane & 15), acl = lane >> 4, ar7 = ar & 7;
    const int br_off = (lane & 7) + ((lane & 16) >> 1), bcl = (lane >> 3) & 1;
    const int rg = lane >> 2, tg = lane & 3;
    const uint32_t abase = sb + (uint32_t)ar * 256u;
    const int cidx = (ncol0 >> 3) + bcl;

    uint32_t buf = 0;
    for (; widx < 1024; widx += 74) {
        const int chunk = widx >> 1, lh = widx & 1;
        const size_t cb = (size_t)chunk * 16384;
        const int nwidx = widx + 74;
        const bool hasnext = nwidx < 1024;
        const int nchunk = nwidx >> 1, nlh = nwidx & 1;
        const size_t ncb = (size_t)nchunk * 16384;

        float4 stg[4];
        if (hasnext) {
            #pragma unroll
            for (int s = 0; s < 2; ++s) {
                const int slot = t + 512 * s;
                const int c = slot & 7, a = (slot >> 3) & 127, ch = slot >> 10;
                const float4* p = (const float4*)(in + (size_t)ch * NSTATE + ncb + a * 128 + nlh * 64 + c * 8);
                stg[2 * s] = p[0];
                stg[2 * s + 1] = p[1];
            }
        }

        float acc0[2][4], acc1[2][4];
        #pragma unroll
        for (int j = 0; j < 2; ++j)
            #pragma unroll
            for (int q = 0; q < 4; ++q) { acc0[j][q] = 0.f; acc1[j][q] = 0.f; }

        const uint32_t bbuf = sb + BH_OFF + buf * 65536u;
        #pragma unroll 1
        for (int ks = 0; ks < 8; ++ks) {
            uint32_t af[4][4], naf2[4], naf3[4];
            const uint32_t aa = abase + (uint32_t)(((ks * 2 + acl) ^ ar7) << 4);
            LDM4(af[0], aa);
            LDM4(af[1], aa + 16384);
            LDM4(af[2], aa + 32768);
            LDM4(af[3], aa + 49152);
            #pragma unroll
            for (int q = 0; q < 4; ++q) { naf2[q] = af[2][q] ^ SGN; naf3[q] = af[3][q] ^ SGN; }

            uint32_t bf[4][4];
            const int row = ks * 16 + br_off;
            const uint32_t ba = bbuf + (uint32_t)row * 128u
                              + (uint32_t)((cidx ^ (row & 7)) << 4);
            LDM4T(bf[0], ba);
            LDM4T(bf[1], ba + 16384);
            LDM4T(bf[2], ba + 32768);
            LDM4T(bf[3], ba + 49152);
            MMA12P(acc0[0], acc1[0], af, naf2, naf3, bf, 0)
            MMA12P(acc0[1], acc1[1], af, naf2, naf3, bf, 1)
        }

        if (hasnext) {
            #pragma unroll
            for (int s = 0; s < 2; ++s) {
                const int slot = t + 512 * s;
                const int c = slot & 7, a = (slot >> 3) & 127, ch = slot >> 10;
                uint4 hi, lo;
                cvt8(stg[2 * s], stg[2 * s + 1], &hi, &lo);
                char* wp = smem + BH_OFF + (buf ^ 1u) * 65536u + (ch * 2) * 16384 + a * 128
                         + ((c ^ (a & 7)) * 16);
                *(uint4*)wp = hi;
                *(uint4*)(wp + 16384) = lo;
            }
            #pragma unroll
            for (int s = 2; s < 4; ++s) {
                const int slot = t + 512 * s;
                const int c = slot & 7, a = (slot >> 3) & 127, ch = slot >> 10;
                const float4* p = (const float4*)(in + (size_t)ch * NSTATE + ncb + a * 128 + nlh * 64 + c * 8);
                uint4 hi, lo;
                cvt8(p[0], p[1], &hi, &lo);
                char* wp = smem + BH_OFF + (buf ^ 1u) * 65536u + (ch * 2) * 16384 + a * 128
                         + ((c ^ (a & 7)) * 16);
                *(uint4*)wp = hi;
                *(uint4*)(wp + 16384) = lo;
            }
        }

        {
            const size_t row0 = (size_t)khalf * 64 + mrow0 + rg;
            float* o0 = out + cb;
            float* o1 = out + NSTATE + cb;
            #pragma unroll
            for (int j = 0; j < 2; ++j) {
                const int n = lh * 64 + ncol0 + j * 8 + tg * 2;
                *(float2*)(o0 + row0 * 128 + n)       = make_float2(acc0[j][0], acc0[j][1]);
                *(float2*)(o0 + (row0 + 8) * 128 + n) = make_float2(acc0[j][2], acc0[j][3]);
                *(float2*)(o1 + row0 * 128 + n)       = make_float2(acc1[j][0], acc1[j][1]);
                *(float2*)(o1 + (row0 + 8) * 128 + n) = make_float2(acc1[j][2], acc1[j][3]);
            }
        }
        __syncthreads();
        buf ^= 1u;
    }
}

// ---------------------------------------------------------------------------
extern "C" void kernel_launch(void* const* d_in, const int* in_sizes, int n_in,
                              void* d_out, int out_size)
{
    const float* state = (const float*)d_in[0];
    const float* U     = (const float*)d_in[1];
    if (n_in >= 2 && in_sizes[0] < in_sizes[1]) {
        const float* tmp = state; state = U; U = tmp;
    }
    float* out = (float*)d_out;

    float* scratch = nullptr;
    cudaGetSymbolAddress((void**)&scratch, g_scratch);
    __nv_bfloat16* ubf = nullptr;
    cudaGetSymbolAddress((void**)&ubf, g_ubf);

    cudaFuncSetAttribute(gate_lowr,  cudaFuncAttributeMaxDynamicSharedMemorySize, (int)SMEM_BYTES_LO);
    cudaFuncSetAttribute(gate_highp, cudaFuncAttributeMaxDynamicSharedMemorySize, (int)SMEM_BYTES_HI);

    prep_u<<<512, 256>>>(U);
    gate_lowr<<<148, 256, SMEM_BYTES_LO>>>(state,   scratch, ubf);            // gate 0
    gate_lowr<<<148, 256, SMEM_BYTES_LO>>>(scratch, out,     ubf + 65536);    // gate 1
    gate_lowr<<<148, 256, SMEM_BYTES_LO>>>(out,     scratch, ubf + 131072);   // gate 2
    gate_highp<<<148, 512, SMEM_BYTES_HI>>>(scratch, out,    ubf + 196608);   // gate 3
}